// round 10
// baseline (speedup 1.0000x reference)
#include <cuda_runtime.h>
#include <cuda_fp16.h>
#include <cstdint>

// ---------------------------------------------------------------------------
// Problem shape / tiling
// ---------------------------------------------------------------------------
#define BSZ    16384
#define DDIM   128
#define TILE_M 256               // rows per item
#define TILE_N 128               // cols per tile step
#define NRT    (BSZ / TILE_M)    // 64 row tiles
#define NCHUNK 16                // col chunks per row tile (1024 cols)
#define NITEMS (NRT * NCHUNK)    // 1024 work items
#define CHUNK_TILES 8
#define GRID_PERS 148
#define NWARPS_G (GRID_PERS * 16)
#define ROWS_PER_CTA 111
#define NEGINF_LO 0x0000FC00u
#define NEGINF_HI 0xFC000000u

// Scratch (device globals; allocation-free rule)
__device__ __align__(128) __half g_Qh[BSZ * DDIM];   // 4 MB
__device__ __align__(128) __half g_Dh[BSZ * DDIM];   // 4 MB
__device__ float    g_pos[BSZ];
__device__ float    g_term1[BSZ];
__device__ unsigned g_rowmax_enc[BSZ];
__device__ float    g_part[160];
__device__ int      g_ctr;
__device__ int      g_prep;
__device__ int      g_done;
__device__ int      g_done2;

// ---------------------------------------------------------------------------
// helpers
// ---------------------------------------------------------------------------
__device__ __forceinline__ uint32_t smem_to_u32(const void* p) {
    uint32_t a;
    asm("{ .reg .u64 t; cvta.to.shared.u64 t, %1; cvt.u32.u64 %0, t; }" : "=r"(a) : "l"(p));
    return a;
}
__device__ __forceinline__ void cpasync16(uint32_t s, const void* g) {
    asm volatile("cp.async.cg.shared.global [%0], [%1], 16;" :: "r"(s), "l"(g));
}
#define CP_COMMIT() asm volatile("cp.async.commit_group;" ::: "memory")
#define CP_WAIT0()  asm volatile("cp.async.wait_group 0;" ::: "memory")

__device__ __forceinline__ void ldsm4(uint32_t* r, uint32_t addr) {
    asm volatile("ldmatrix.sync.aligned.m8n8.x4.shared.b16 {%0,%1,%2,%3}, [%4];"
                 : "=r"(r[0]), "=r"(r[1]), "=r"(r[2]), "=r"(r[3]) : "r"(addr));
}
__device__ __forceinline__ void mma16816h(uint32_t* c, const uint32_t* a, uint32_t b0, uint32_t b1) {
    asm volatile("mma.sync.aligned.m16n8k16.row.col.f16.f16.f16.f16 "
                 "{%0,%1}, {%2,%3,%4,%5}, {%6,%7}, {%0,%1};"
                 : "+r"(c[0]), "+r"(c[1])
                 : "r"(a[0]), "r"(a[1]), "r"(a[2]), "r"(a[3]), "r"(b0), "r"(b1));
}
__device__ __forceinline__ uint32_t hmax2(uint32_t a, uint32_t b) {
    uint32_t d;
    asm("max.f16x2 %0, %1, %2;" : "=r"(d) : "r"(a), "r"(b));
    return d;
}
__device__ __forceinline__ float softplusf(float x) {
    return x > 20.0f ? x : log1pf(__expf(x));
}
__device__ __forceinline__ unsigned enc_f(float x) {
    unsigned u = __float_as_uint(x);
    return (u & 0x80000000u) ? ~u : (u | 0x80000000u);
}
__device__ __forceinline__ float dec_f(unsigned e) {
    unsigned u = (e & 0x80000000u) ? (e & 0x7FFFFFFFu) : ~e;
    return __uint_as_float(u);
}
__device__ __forceinline__ void spin_until(int* ctr, int target) {
    while (atomicAdd(ctr, 0) < target) { __nanosleep(64); }
}

// ---------------------------------------------------------------------------
// smem: ONLY the A tile, double-buffered (256 rows x 256 B, XOR-swizzled)
// ---------------------------------------------------------------------------
#define SMEM_A0    0
#define SMEM_A1    65536
#define SMEM_TOTAL 131072

__device__ __forceinline__ void load_tileA_sw(uint32_t dst, const __half* src,
                                              int rowBase, int tid) {
    const char* s = (const char*)(src + (size_t)rowBase * DDIM);
    #pragma unroll
    for (int i = 0; i < 8; ++i) {
        int e = tid + 512 * i;         // 4096 chunks (256 rows x 16)
        int r = e >> 4;
        int c = e & 15;
        cpasync16(dst + r * 256 + ((c ^ (r & 7)) << 4), s + (size_t)r * 256 + c * 16);
    }
}

// ---------------------------------------------------------------------------
// ONE persistent kernel
// ---------------------------------------------------------------------------
__global__ void __launch_bounds__(512, 1)
mega_kernel(const float* __restrict__ q, const float* __restrict__ d,
            const float* __restrict__ nd, float* __restrict__ out) {
    extern __shared__ __align__(1024) char smem[];
    __shared__ int s_item2[2];
    const uint32_t sb = smem_to_u32(smem);
    const int tid  = threadIdx.x;
    const int lane = tid & 31;
    const int wid  = tid >> 5;
    const int wm   = wid >> 2;        // 0..3
    const int wn   = wid & 3;         // 0..3  (== SMSP id)

    // ---------------- Phase 0: prep ----------------------------------------
    {
        int gw = blockIdx.x * 16 + wid;
        for (int row = gw; row < BSZ; row += NWARPS_G) {
            const float4 qv = *(const float4*)(q  + (size_t)row * DDIM + lane * 4);
            const float4 dv = *(const float4*)(d  + (size_t)row * DDIM + lane * 4);
            const float4 nv = *(const float4*)(nd + (size_t)row * DDIM + lane * 4);

            __half2* qdst = (__half2*)(g_Qh + (size_t)row * DDIM + lane * 4);
            qdst[0] = __floats2half2_rn(qv.x, qv.y);
            qdst[1] = __floats2half2_rn(qv.z, qv.w);
            __half2* ddst = (__half2*)(g_Dh + (size_t)row * DDIM + lane * 4);
            ddst[0] = __floats2half2_rn(dv.x, dv.y);
            ddst[1] = __floats2half2_rn(dv.z, dv.w);

            float pos = qv.x * dv.x + qv.y * dv.y + qv.z * dv.z + qv.w * dv.w;
            float neg = qv.x * nv.x + qv.y * nv.y + qv.z * nv.z + qv.w * nv.w;
            #pragma unroll
            for (int off = 16; off > 0; off >>= 1) {
                pos += __shfl_xor_sync(0xFFFFFFFFu, pos, off);
                neg += __shfl_xor_sync(0xFFFFFFFFu, neg, off);
            }
            if (lane == 0) {
                g_pos[row]   = pos;
                g_term1[row] = softplusf(neg - pos);
                g_rowmax_enc[row] = 0u;
            }
        }
    }
    __threadfence();
    __syncthreads();
    if (tid == 0) { atomicAdd(&g_prep, 1); spin_until(&g_prep, GRID_PERS); }
    __syncthreads();

    // ---------------- Phase 1: persistent max-GEMM --------------------------
    // A via smem/ldsm (swizzled); B fragments loaded DIRECTLY from g_Dh.
    const int xr  = lane & 7;
    const int hcA = (lane >> 4) & 1;
    const uint32_t aRow = (uint32_t)((wm * 64 + (lane & 15)) * 256);

    // per-thread B fragment base: row n = wn*32 + lane/4, byte (lane%4)*4
    const char* const bThr = (const char*)g_Dh +
        ((size_t)(wn * 32 + (lane >> 2)) * 256) + (size_t)((lane & 3) * 4);

    // prologue: pop first item, stage its A, pop second
    if (tid == 0) s_item2[0] = atomicAdd(&g_ctr, 1);
    __syncthreads();
    int cur = s_item2[0];
    int abuf = 0, pb2 = 1;
    if (cur < NITEMS) {
        load_tileA_sw(sb + SMEM_A0, g_Qh, (cur >> 4) * TILE_M, tid);
        CP_COMMIT();
        if (tid == 0) s_item2[1] = atomicAdd(&g_ctr, 1);
    }

    while (cur < NITEMS) {
        CP_WAIT0();
        __syncthreads();                       // A(cur) visible; s_item2[pb2] visible
        const int nxt = s_item2[pb2];
        if (nxt < NITEMS) {
            load_tileA_sw(sb + (abuf ? SMEM_A0 : SMEM_A1), g_Qh, (nxt >> 4) * TILE_M, tid);
            CP_COMMIT();
            if (tid == 0) s_item2[pb2 ^ 1] = atomicAdd(&g_ctr, 1);
        }
        pb2 ^= 1;

        const int rt = cur >> 4;
        const int cc8 = (cur & 15) * CHUNK_TILES;
        const int rowBase = rt * TILE_M;
        const uint32_t aBufBase = sb + (abuf ? SMEM_A1 : SMEM_A0) + aRow;
        const char* bp = bThr + (size_t)cc8 * 32768;   // tile 0 of this item

        uint32_t rmax2[4][2];
        #pragma unroll
        for (int mi = 0; mi < 4; ++mi) { rmax2[mi][0] = 0xFC00FC00u; rmax2[mi][1] = 0xFC00FC00u; }

        // preload B fragments for (tile 0, ks 0)
        uint32_t bb[2][4][2];
        #pragma unroll
        for (int ni = 0; ni < 4; ++ni) {
            bb[0][ni][0] = __ldg((const uint32_t*)(bp + ni * 2048));
            bb[0][ni][1] = __ldg((const uint32_t*)(bp + ni * 2048 + 16));
        }

        for (int j = 0; j < CHUNK_TILES; ++j) {
            uint32_t acc[4][4][2];
            #pragma unroll
            for (int mi = 0; mi < 4; ++mi)
                #pragma unroll
                for (int ni = 0; ni < 4; ++ni) { acc[mi][ni][0] = 0u; acc[mi][ni][1] = 0u; }

            #pragma unroll
            for (int ks = 0; ks < 8; ++ks) {
                uint32_t (*bcur)[2] = bb[ks & 1];
                uint32_t (*bnxt)[2] = bb[(ks + 1) & 1];
                // prefetch next step's B fragments
                if (ks < 7) {
                    #pragma unroll
                    for (int ni = 0; ni < 4; ++ni) {
                        bnxt[ni][0] = __ldg((const uint32_t*)(bp + ni * 2048 + (ks + 1) * 32));
                        bnxt[ni][1] = __ldg((const uint32_t*)(bp + ni * 2048 + (ks + 1) * 32 + 16));
                    }
                } else if (j < CHUNK_TILES - 1) {
                    #pragma unroll
                    for (int ni = 0; ni < 4; ++ni) {
                        bnxt[ni][0] = __ldg((const uint32_t*)(bp + ni * 2048 + 32768));
                        bnxt[ni][1] = __ldg((const uint32_t*)(bp + ni * 2048 + 32768 + 16));
                    }
                }
                // A fragments from smem
                const uint32_t aCh = (uint32_t)((((ks * 2 + hcA) ^ xr)) << 4);
                uint32_t a[4][4];
                #pragma unroll
                for (int mi = 0; mi < 4; ++mi)
                    ldsm4(a[mi], aBufBase + (uint32_t)(mi * 4096) + aCh);
                #pragma unroll
                for (int mi = 0; mi < 4; ++mi)
                    #pragma unroll
                    for (int ni = 0; ni < 4; ++ni)
                        mma16816h(acc[mi][ni], a[mi], bcur[ni][0], bcur[ni][1]);
            }

            // diagonal mask: col tile ct = cc8 + j hits diag when ct == 2*rt or 2*rt+1
            {
                const int dt = (cc8 + j) - 2 * rt;
                if (dt == 0 || dt == 1) {
                    const int coff = dt * 128;
                    #pragma unroll
                    for (int mi = 0; mi < 4; ++mi) {
                        int r0 = wm * 64 + mi * 16 + (lane >> 2);
                        #pragma unroll
                        for (int ni = 0; ni < 4; ++ni) {
                            int c0 = wn * 32 + ni * 8 + (lane & 3) * 2 + coff;
                            if (c0     == r0)     acc[mi][ni][0] = (acc[mi][ni][0] & 0xFFFF0000u) | NEGINF_LO;
                            if (c0 + 1 == r0)     acc[mi][ni][0] = (acc[mi][ni][0] & 0x0000FFFFu) | NEGINF_HI;
                            if (c0     == r0 + 8) acc[mi][ni][1] = (acc[mi][ni][1] & 0xFFFF0000u) | NEGINF_LO;
                            if (c0 + 1 == r0 + 8) acc[mi][ni][1] = (acc[mi][ni][1] & 0x0000FFFFu) | NEGINF_HI;
                        }
                    }
                }
            }
            #pragma unroll
            for (int mi = 0; mi < 4; ++mi)
                #pragma unroll
                for (int ni = 0; ni < 4; ++ni) {
                    rmax2[mi][0] = hmax2(rmax2[mi][0], acc[mi][ni][0]);
                    rmax2[mi][1] = hmax2(rmax2[mi][1], acc[mi][ni][1]);
                }
            bp += 32768;   // next 128-col tile
        }

        // item epilogue: collapse + quad reduce + atomicMax (exact, deterministic)
        {
            float rmax[8];
            #pragma unroll
            for (int mi = 0; mi < 4; ++mi)
                #pragma unroll
                for (int rr = 0; rr < 2; ++rr) {
                    __half2 h = *(__half2*)&rmax2[mi][rr];
                    rmax[mi * 2 + rr] = fmaxf(__low2float(h), __high2float(h));
                }
            #pragma unroll
            for (int i = 0; i < 8; ++i) {
                rmax[i] = fmaxf(rmax[i], __shfl_xor_sync(0xFFFFFFFFu, rmax[i], 1));
                rmax[i] = fmaxf(rmax[i], __shfl_xor_sync(0xFFFFFFFFu, rmax[i], 2));
            }
            if ((lane & 3) == 0) {
                #pragma unroll
                for (int mi = 0; mi < 4; ++mi) {
                    int rA = rowBase + wm * 64 + mi * 16 + (lane >> 2);
                    atomicMax(&g_rowmax_enc[rA],     enc_f(rmax[mi * 2 + 0]));
                    atomicMax(&g_rowmax_enc[rA + 8], enc_f(rmax[mi * 2 + 1]));
                }
            }
        }

        cur = nxt;
        abuf ^= 1;
    }

    // ---------------- grid barrier 2 ----------------------------------------
    __threadfence();
    __syncthreads();
    if (tid == 0) { atomicAdd(&g_done, 1); spin_until(&g_done, GRID_PERS); }
    __syncthreads();
    __threadfence();

    // ---------------- Phase 2a: per-CTA deterministic partial sum -----------
    {
        float* sum = (float*)smem;   // A region is dead now
        const int r0 = blockIdx.x * ROWS_PER_CTA;
        const int r1 = (r0 + ROWS_PER_CTA < BSZ) ? (r0 + ROWS_PER_CTA) : BSZ;
        float s = 0.0f;
        for (int b = r0 + tid; b < r1; b += 512)
            s += g_term1[b] + softplusf(dec_f(g_rowmax_enc[b]) - g_pos[b]);
        sum[tid] = s;
        __syncthreads();
        #pragma unroll
        for (int off = 256; off > 0; off >>= 1) {
            if (tid < off) sum[tid] += sum[tid + off];
            __syncthreads();
        }
        if (tid == 0) { g_part[blockIdx.x] = sum[0]; __threadfence(); }
    }

    // ---------------- Phase 2b: last CTA combines ---------------------------
    __syncthreads();
    if (tid == 0) s_item2[0] = (atomicAdd(&g_done2, 1) == GRID_PERS - 1) ? 1 : 0;
    __syncthreads();
    if (s_item2[0]) {
        __threadfence();
        float* sum = (float*)smem;
        sum[tid] = (tid < GRID_PERS) ? g_part[tid] : 0.0f;
        __syncthreads();
        #pragma unroll
        for (int off = 256; off > 0; off >>= 1) {
            if (tid < off) sum[tid] += sum[tid + off];
            __syncthreads();
        }
        if (tid == 0) {
            out[0] = sum[0] / (2.0f * (float)BSZ);
            g_ctr = 0; g_prep = 0; g_done = 0; g_done2 = 0;
            __threadfence();
        }
    }
}

// ---------------------------------------------------------------------------
extern "C" void kernel_launch(void* const* d_in, const int* in_sizes, int n_in,
                              void* d_out, int out_size) {
    const float* q  = (const float*)d_in[0];
    const float* dd = (const float*)d_in[1];
    const float* nd = (const float*)d_in[2];
    float* out = (float*)d_out;

    cudaFuncSetAttribute(mega_kernel, cudaFuncAttributeMaxDynamicSharedMemorySize, SMEM_TOTAL);
    mega_kernel<<<GRID_PERS, 512, SMEM_TOTAL>>>(q, dd, nd, out);
}

// round 11
// speedup vs baseline: 2.0520x; 2.0520x over previous
#include <cuda_runtime.h>
#include <cuda_fp16.h>
#include <cstdint>

// ---------------------------------------------------------------------------
// Problem shape / tiling
// ---------------------------------------------------------------------------
#define BSZ    16384
#define DDIM   128
#define TILE_M 512               // rows per item (CTA tile M)
#define TILE_N 128               // cols per tile step
#define NRT    (BSZ / TILE_M)    // 32 row tiles
#define NCHUNK 32                // col chunks per row tile (512 cols each)
#define NITEMS (NRT * NCHUNK)    // 1024 work items
#define CHUNK_TILES 4            // 128-col tiles per chunk
#define GRID_PERS 148
#define NWARPS_G (GRID_PERS * 16)
#define ROWS_PER_CTA 111
#define NEGINF_LO 0x0000FC00u
#define NEGINF_HI 0xFC000000u

// Scratch (device globals; allocation-free rule)
__device__ __align__(128) __half g_Qh[BSZ * DDIM];   // 4 MB
__device__ __align__(128) __half g_Dh[BSZ * DDIM];   // 4 MB
__device__ float    g_pos[BSZ];
__device__ float    g_term1[BSZ];
__device__ unsigned g_rowmax_enc[BSZ];
__device__ float    g_part[160];
__device__ int      g_ctr;
__device__ int      g_prep;
__device__ int      g_done;
__device__ int      g_done2;

// ---------------------------------------------------------------------------
// helpers
// ---------------------------------------------------------------------------
__device__ __forceinline__ uint32_t smem_to_u32(const void* p) {
    uint32_t a;
    asm("{ .reg .u64 t; cvta.to.shared.u64 t, %1; cvt.u32.u64 %0, t; }" : "=r"(a) : "l"(p));
    return a;
}
__device__ __forceinline__ void cpasync16(uint32_t s, const void* g) {
    asm volatile("cp.async.cg.shared.global [%0], [%1], 16;" :: "r"(s), "l"(g));
}
#define CP_COMMIT() asm volatile("cp.async.commit_group;" ::: "memory")
#define CP_WAIT0()  asm volatile("cp.async.wait_group 0;" ::: "memory")
#define CP_WAIT1()  asm volatile("cp.async.wait_group 1;" ::: "memory")

__device__ __forceinline__ void ldsm4(uint32_t* r, uint32_t addr) {
    asm volatile("ldmatrix.sync.aligned.m8n8.x4.shared.b16 {%0,%1,%2,%3}, [%4];"
                 : "=r"(r[0]), "=r"(r[1]), "=r"(r[2]), "=r"(r[3]) : "r"(addr));
}
__device__ __forceinline__ void mma16816h(uint32_t* c, const uint32_t* a, uint32_t b0, uint32_t b1) {
    asm volatile("mma.sync.aligned.m16n8k16.row.col.f16.f16.f16.f16 "
                 "{%0,%1}, {%2,%3,%4,%5}, {%6,%7}, {%0,%1};"
                 : "+r"(c[0]), "+r"(c[1])
                 : "r"(a[0]), "r"(a[1]), "r"(a[2]), "r"(a[3]), "r"(b0), "r"(b1));
}
__device__ __forceinline__ uint32_t hmax2(uint32_t a, uint32_t b) {
    uint32_t d;
    asm("max.f16x2 %0, %1, %2;" : "=r"(d) : "r"(a), "r"(b));
    return d;
}
__device__ __forceinline__ float softplusf(float x) {
    return x > 20.0f ? x : log1pf(__expf(x));
}
__device__ __forceinline__ unsigned enc_f(float x) {
    unsigned u = __float_as_uint(x);
    return (u & 0x80000000u) ? ~u : (u | 0x80000000u);
}
__device__ __forceinline__ float dec_f(unsigned e) {
    unsigned u = (e & 0x80000000u) ? (e & 0x7FFFFFFFu) : ~e;
    return __uint_as_float(u);
}
__device__ __forceinline__ void spin_until(int* ctr, int target) {
    while (atomicAdd(ctr, 0) < target) { __nanosleep(64); }
}

// ---------------------------------------------------------------------------
// smem: A single (512 rows x 256B = 128KB) + B ring x3 (128 rows x 256B each)
// ---------------------------------------------------------------------------
#define SMEM_A     0
#define SMEM_BR    131072          // + slot * 32768, 3 slots
#define SMEM_TOTAL 229376

// swizzle: 16B chunk c of row r lives at chunk (c ^ (r & 7))
__device__ __forceinline__ void load_tileA_sw(uint32_t dst, const __half* src,
                                              int rowBase, int tid) {
    const char* s = (const char*)(src + (size_t)rowBase * DDIM);
    #pragma unroll
    for (int i = 0; i < 16; ++i) {
        int e = tid + 512 * i;         // 8192 chunks (512 rows x 16)
        int r = e >> 4;
        int c = e & 15;
        cpasync16(dst + r * 256 + ((c ^ (r & 7)) << 4), s + (size_t)r * 256 + c * 16);
    }
}
__device__ __forceinline__ void load_tileB_sw(uint32_t dst, const __half* src,
                                              int rowBase, int tid) {
    const char* s = (const char*)(src + (size_t)rowBase * DDIM);
    #pragma unroll
    for (int i = 0; i < 4; ++i) {
        int e = tid + 512 * i;         // 2048 chunks (128 rows x 16)
        int r = e >> 4;
        int c = e & 15;
        cpasync16(dst + r * 256 + ((c ^ (r & 7)) << 4), s + (size_t)r * 256 + c * 16);
    }
}

// ---------------------------------------------------------------------------
// ONE persistent kernel
// ---------------------------------------------------------------------------
__global__ void __launch_bounds__(512, 1)
mega_kernel(const float* __restrict__ q, const float* __restrict__ d,
            const float* __restrict__ nd, float* __restrict__ out) {
    extern __shared__ __align__(1024) char smem[];
    __shared__ int s_next;
    const uint32_t sb = smem_to_u32(smem);
    const int tid  = threadIdx.x;
    const int lane = tid & 31;
    const int wid  = tid >> 5;
    const int wm   = wid >> 1;        // 0..7  (M position, 64 rows each)
    const int wn   = wid & 1;         // 0..1  (N position, 64 cols each)

    // ---------------- Phase 0: prep ----------------------------------------
    {
        int gw = blockIdx.x * 16 + wid;
        for (int row = gw; row < BSZ; row += NWARPS_G) {
            const float4 qv = *(const float4*)(q  + (size_t)row * DDIM + lane * 4);
            const float4 dv = *(const float4*)(d  + (size_t)row * DDIM + lane * 4);
            const float4 nv = *(const float4*)(nd + (size_t)row * DDIM + lane * 4);

            __half2* qdst = (__half2*)(g_Qh + (size_t)row * DDIM + lane * 4);
            qdst[0] = __floats2half2_rn(qv.x, qv.y);
            qdst[1] = __floats2half2_rn(qv.z, qv.w);
            __half2* ddst = (__half2*)(g_Dh + (size_t)row * DDIM + lane * 4);
            ddst[0] = __floats2half2_rn(dv.x, dv.y);
            ddst[1] = __floats2half2_rn(dv.z, dv.w);

            float pos = qv.x * dv.x + qv.y * dv.y + qv.z * dv.z + qv.w * dv.w;
            float neg = qv.x * nv.x + qv.y * nv.y + qv.z * nv.z + qv.w * nv.w;
            #pragma unroll
            for (int off = 16; off > 0; off >>= 1) {
                pos += __shfl_xor_sync(0xFFFFFFFFu, pos, off);
                neg += __shfl_xor_sync(0xFFFFFFFFu, neg, off);
            }
            if (lane == 0) {
                g_pos[row]   = pos;
                g_term1[row] = softplusf(neg - pos);
                g_rowmax_enc[row] = 0u;
            }
        }
    }
    __threadfence();
    __syncthreads();
    if (tid == 0) { atomicAdd(&g_prep, 1); spin_until(&g_prep, GRID_PERS); }
    __syncthreads();

    // ---------------- Phase 1: persistent max-GEMM --------------------------
    const int xr  = lane & 7;
    const int hcA = (lane >> 4) & 1;
    const int hcB = (lane >> 3) & 1;
    const uint32_t aRow    = (uint32_t)((wm * 64 + (lane & 15)) * 256);
    const uint32_t bRowOff = (uint32_t)((wn * 64 + ((lane >> 4) << 3) + (lane & 7)) * 256);

    if (tid == 0) s_next = atomicAdd(&g_ctr, 1);
    __syncthreads();
    int cur = s_next;

    while (cur < NITEMS) {
        // all warps are past the previous item's reads here
        const int rt  = cur >> 5;               // row tile 0..31
        const int cc  = cur & 31;               // col chunk 0..31
        const int rowBase = rt * TILE_M;
        const int ct0 = cc * CHUNK_TILES;       // first global 128-col tile

        if (tid == 0) s_next = atomicAdd(&g_ctr, 1);
        // group 1: A + B0 ; group 2: B1
        load_tileA_sw(sb + SMEM_A, g_Qh, rowBase, tid);
        load_tileB_sw(sb + SMEM_BR, g_Dh, (ct0 + 0) * TILE_N, tid);
        CP_COMMIT();
        load_tileB_sw(sb + SMEM_BR + 32768, g_Dh, (ct0 + 1) * TILE_N, tid);
        CP_COMMIT();

        uint32_t rmax2[4][2];
        #pragma unroll
        for (int mi = 0; mi < 4; ++mi) { rmax2[mi][0] = 0xFC00FC00u; rmax2[mi][1] = 0xFC00FC00u; }

        #pragma unroll
        for (int j = 0; j < CHUNK_TILES; ++j) {
            if (j < 3) { CP_WAIT1(); } else { CP_WAIT0(); }
            __syncthreads();
            if (j < 2) {
                // prefetch B(j+2) into ring slot (j+2)%3
                load_tileB_sw(sb + SMEM_BR + (uint32_t)(((j + 2) % 3) * 32768),
                              g_Dh, (ct0 + j + 2) * TILE_N, tid);
                CP_COMMIT();
            }
            const uint32_t aBufBase = sb + SMEM_A + aRow;
            const uint32_t bBufBase = sb + SMEM_BR + (uint32_t)((j % 3) * 32768) + bRowOff;

            uint32_t acc[4][8][2];
            #pragma unroll
            for (int mi = 0; mi < 4; ++mi)
                #pragma unroll
                for (int ni = 0; ni < 8; ++ni) { acc[mi][ni][0] = 0u; acc[mi][ni][1] = 0u; }

            #pragma unroll
            for (int ks = 0; ks < 8; ++ks) {
                const uint32_t aCh = (uint32_t)(((ks * 2 + hcA) ^ xr) << 4);
                const uint32_t bCh = (uint32_t)(((ks * 2 + hcB) ^ xr) << 4);
                uint32_t a[4][4];
                #pragma unroll
                for (int mi = 0; mi < 4; ++mi)
                    ldsm4(a[mi], aBufBase + (uint32_t)(mi * 4096) + aCh);
                uint32_t b[4][4];
                #pragma unroll
                for (int np = 0; np < 4; ++np)
                    ldsm4(b[np], bBufBase + (uint32_t)(np * 4096) + bCh);
                #pragma unroll
                for (int mi = 0; mi < 4; ++mi)
                    #pragma unroll
                    for (int np = 0; np < 4; ++np) {
                        mma16816h(acc[mi][np * 2 + 0], a[mi], b[np][0], b[np][1]);
                        mma16816h(acc[mi][np * 2 + 1], a[mi], b[np][2], b[np][3]);
                    }
            }

            // diagonal mask: global col tile ct = ct0+j hits diag when dt = ct-4*rt in 0..3
            {
                const int dt = (ct0 + j) - 4 * rt;
                if (dt >= 0 && dt <= 3) {
                    const int coff = dt * 128;
                    #pragma unroll
                    for (int mi = 0; mi < 4; ++mi) {
                        int r0 = wm * 64 + mi * 16 + (lane >> 2);
                        #pragma unroll
                        for (int ni = 0; ni < 8; ++ni) {
                            int c0 = wn * 64 + ni * 8 + (lane & 3) * 2 + coff;
                            if (c0     == r0)     acc[mi][ni][0] = (acc[mi][ni][0] & 0xFFFF0000u) | NEGINF_LO;
                            if (c0 + 1 == r0)     acc[mi][ni][0] = (acc[mi][ni][0] & 0x0000FFFFu) | NEGINF_HI;
                            if (c0     == r0 + 8) acc[mi][ni][1] = (acc[mi][ni][1] & 0xFFFF0000u) | NEGINF_LO;
                            if (c0 + 1 == r0 + 8) acc[mi][ni][1] = (acc[mi][ni][1] & 0x0000FFFFu) | NEGINF_HI;
                        }
                    }
                }
            }
            #pragma unroll
            for (int mi = 0; mi < 4; ++mi)
                #pragma unroll
                for (int ni = 0; ni < 8; ++ni) {
                    rmax2[mi][0] = hmax2(rmax2[mi][0], acc[mi][ni][0]);
                    rmax2[mi][1] = hmax2(rmax2[mi][1], acc[mi][ni][1]);
                }
        }

        // item epilogue: collapse + quad reduce + atomicMax (exact, deterministic)
        {
            float rmax[8];
            #pragma unroll
            for (int mi = 0; mi < 4; ++mi)
                #pragma unroll
                for (int rr = 0; rr < 2; ++rr) {
                    __half2 h = *(__half2*)&rmax2[mi][rr];
                    rmax[mi * 2 + rr] = fmaxf(__low2float(h), __high2float(h));
                }
            #pragma unroll
            for (int i = 0; i < 8; ++i) {
                rmax[i] = fmaxf(rmax[i], __shfl_xor_sync(0xFFFFFFFFu, rmax[i], 1));
                rmax[i] = fmaxf(rmax[i], __shfl_xor_sync(0xFFFFFFFFu, rmax[i], 2));
            }
            if ((lane & 3) == 0) {
                #pragma unroll
                for (int mi = 0; mi < 4; ++mi) {
                    int rA = rowBase + wm * 64 + mi * 16 + (lane >> 2);
                    atomicMax(&g_rowmax_enc[rA],     enc_f(rmax[mi * 2 + 0]));
                    atomicMax(&g_rowmax_enc[rA + 8], enc_f(rmax[mi * 2 + 1]));
                }
            }
        }

        cur = s_next;          // visible: last __syncthreads was after the write
        __syncthreads();       // everyone done reading A/B before next item reloads
    }

    // ---------------- grid barrier 2 ----------------------------------------
    __threadfence();
    __syncthreads();
    if (tid == 0) { atomicAdd(&g_done, 1); spin_until(&g_done, GRID_PERS); }
    __syncthreads();
    __threadfence();

    // ---------------- Phase 2a: per-CTA deterministic partial sum -----------
    {
        float* sum = (float*)smem;
        const int r0 = blockIdx.x * ROWS_PER_CTA;
        const int r1 = (r0 + ROWS_PER_CTA < BSZ) ? (r0 + ROWS_PER_CTA) : BSZ;
        float s = 0.0f;
        for (int b = r0 + tid; b < r1; b += 512)
            s += g_term1[b] + softplusf(dec_f(g_rowmax_enc[b]) - g_pos[b]);
        sum[tid] = s;
        __syncthreads();
        #pragma unroll
        for (int off = 256; off > 0; off >>= 1) {
            if (tid < off) sum[tid] += sum[tid + off];
            __syncthreads();
        }
        if (tid == 0) { g_part[blockIdx.x] = sum[0]; __threadfence(); }
    }

    // ---------------- Phase 2b: last CTA combines ---------------------------
    __syncthreads();
    if (tid == 0) s_next = (atomicAdd(&g_done2, 1) == GRID_PERS - 1) ? 1 : 0;
    __syncthreads();
    if (s_next) {
        __threadfence();
        float* sum = (float*)smem;
        sum[tid] = (tid < GRID_PERS) ? g_part[tid] : 0.0f;
        __syncthreads();
        #pragma unroll
        for (int off = 256; off > 0; off >>= 1) {
            if (tid < off) sum[tid] += sum[tid + off];
            __syncthreads();
        }
        if (tid == 0) {
            out[0] = sum[0] / (2.0f * (float)BSZ);
            g_ctr = 0; g_prep = 0; g_done = 0; g_done2 = 0;
            __threadfence();
        }
    }
}

// ---------------------------------------------------------------------------
extern "C" void kernel_launch(void* const* d_in, const int* in_sizes, int n_in,
                              void* d_out, int out_size) {
    const float* q  = (const float*)d_in[0];
    const float* dd = (const float*)d_in[1];
    const float* nd = (const float*)d_in[2];
    float* out = (float*)d_out;

    cudaFuncSetAttribute(mega_kernel, cudaFuncAttributeMaxDynamicSharedMemorySize, SMEM_TOTAL);
    mega_kernel<<<GRID_PERS, 512, SMEM_TOTAL>>>(q, dd, nd, out);
}

// round 12
// speedup vs baseline: 2.1416x; 1.0437x over previous
#include <cuda_runtime.h>
#include <cuda_fp16.h>
#include <cstdint>

// ---------------------------------------------------------------------------
// Problem shape / tiling
// ---------------------------------------------------------------------------
#define BSZ    16384
#define DDIM   128
#define TILE_M 512               // rows per row-tile
#define TILE_N 128               // cols per tile step
#define NRT    (BSZ / TILE_M)    // 32 row tiles
#define NCHUNK 32                // items per row tile (4 col tiles each)
#define NITEMS (NRT * NCHUNK)    // 1024 work items
#define GRID_PERS 148
#define NWARPS_G (GRID_PERS * 16)
#define ROWS_PER_CTA 111
#define NEGINF_LO 0x0000FC00u
#define NEGINF_HI 0xFC000000u

// Scratch (device globals; allocation-free rule)
__device__ __align__(128) __half g_Qh[BSZ * DDIM];   // 4 MB
__device__ __align__(128) __half g_Dh[BSZ * DDIM];   // 4 MB
__device__ float    g_pos[BSZ];
__device__ float    g_term1[BSZ];
__device__ unsigned g_rowmax_enc[BSZ];
__device__ float    g_part[160];
__device__ int      g_prep;
__device__ int      g_done;
__device__ int      g_done2;

// ---------------------------------------------------------------------------
// helpers
// ---------------------------------------------------------------------------
__device__ __forceinline__ uint32_t smem_to_u32(const void* p) {
    uint32_t a;
    asm("{ .reg .u64 t; cvta.to.shared.u64 t, %1; cvt.u32.u64 %0, t; }" : "=r"(a) : "l"(p));
    return a;
}
__device__ __forceinline__ void cpasync16(uint32_t s, const void* g) {
    asm volatile("cp.async.cg.shared.global [%0], [%1], 16;" :: "r"(s), "l"(g));
}
#define CP_COMMIT() asm volatile("cp.async.commit_group;" ::: "memory")
#define CP_WAIT0()  asm volatile("cp.async.wait_group 0;" ::: "memory")
#define CP_WAIT1()  asm volatile("cp.async.wait_group 1;" ::: "memory")

__device__ __forceinline__ void ldsm4(uint32_t* r, uint32_t addr) {
    asm volatile("ldmatrix.sync.aligned.m8n8.x4.shared.b16 {%0,%1,%2,%3}, [%4];"
                 : "=r"(r[0]), "=r"(r[1]), "=r"(r[2]), "=r"(r[3]) : "r"(addr));
}
__device__ __forceinline__ void mma16816h(uint32_t* c, const uint32_t* a, uint32_t b0, uint32_t b1) {
    asm volatile("mma.sync.aligned.m16n8k16.row.col.f16.f16.f16.f16 "
                 "{%0,%1}, {%2,%3,%4,%5}, {%6,%7}, {%0,%1};"
                 : "+r"(c[0]), "+r"(c[1])
                 : "r"(a[0]), "r"(a[1]), "r"(a[2]), "r"(a[3]), "r"(b0), "r"(b1));
}
__device__ __forceinline__ uint32_t hmax2(uint32_t a, uint32_t b) {
    uint32_t d;
    asm("max.f16x2 %0, %1, %2;" : "=r"(d) : "r"(a), "r"(b));
    return d;
}
__device__ __forceinline__ float softplusf(float x) {
    return x > 20.0f ? x : log1pf(__expf(x));
}
__device__ __forceinline__ unsigned enc_f(float x) {
    unsigned u = __float_as_uint(x);
    return (u & 0x80000000u) ? ~u : (u | 0x80000000u);
}
__device__ __forceinline__ float dec_f(unsigned e) {
    unsigned u = (e & 0x80000000u) ? (e & 0x7FFFFFFFu) : ~e;
    return __uint_as_float(u);
}
__device__ __forceinline__ void spin_until(int* ctr, int target) {
    while (atomicAdd(ctr, 0) < target) { __nanosleep(64); }
}

// ---------------------------------------------------------------------------
// smem: A (512 rows x 256B = 128KB) + B ring x3 (128 rows x 256B each)
// ---------------------------------------------------------------------------
#define SMEM_A     0
#define SMEM_BR    131072          // + slot * 32768, 3 slots
#define SMEM_TOTAL 229376

// swizzle: 16B chunk c of row r lives at chunk (c ^ (r & 7))
__device__ __forceinline__ void load_tileA_sw(uint32_t dst, const __half* src,
                                              int rowBase, int tid) {
    const char* s = (const char*)(src + (size_t)rowBase * DDIM);
    #pragma unroll
    for (int i = 0; i < 16; ++i) {
        int e = tid + 512 * i;         // 8192 chunks (512 rows x 16)
        int r = e >> 4;
        int c = e & 15;
        cpasync16(dst + r * 256 + ((c ^ (r & 7)) << 4), s + (size_t)r * 256 + c * 16);
    }
}
__device__ __forceinline__ void load_tileB_sw(uint32_t dst, const __half* src,
                                              int rowBase, int tid) {
    const char* s = (const char*)(src + (size_t)rowBase * DDIM);
    #pragma unroll
    for (int i = 0; i < 4; ++i) {
        int e = tid + 512 * i;         // 2048 chunks (128 rows x 16)
        int r = e >> 4;
        int c = e & 15;
        cpasync16(dst + r * 256 + ((c ^ (r & 7)) << 4), s + (size_t)r * 256 + c * 16);
    }
}

// ---------------------------------------------------------------------------
// ONE persistent kernel; static contiguous item partition, A reused per segment
// ---------------------------------------------------------------------------
__global__ void __launch_bounds__(512, 1)
mega_kernel(const float* __restrict__ q, const float* __restrict__ d,
            const float* __restrict__ nd, float* __restrict__ out) {
    extern __shared__ __align__(1024) char smem[];
    __shared__ int s_flag;
    const uint32_t sb = smem_to_u32(smem);
    const int tid  = threadIdx.x;
    const int lane = tid & 31;
    const int wid  = tid >> 5;
    const int wm   = wid >> 1;        // 0..7  (M position, 64 rows each)
    const int wn   = wid & 1;         // 0..1  (N position, 64 cols each)

    // ---------------- Phase 0: prep ----------------------------------------
    {
        int gw = blockIdx.x * 16 + wid;
        for (int row = gw; row < BSZ; row += NWARPS_G) {
            const float4 qv = *(const float4*)(q  + (size_t)row * DDIM + lane * 4);
            const float4 dv = *(const float4*)(d  + (size_t)row * DDIM + lane * 4);
            const float4 nv = *(const float4*)(nd + (size_t)row * DDIM + lane * 4);

            __half2* qdst = (__half2*)(g_Qh + (size_t)row * DDIM + lane * 4);
            qdst[0] = __floats2half2_rn(qv.x, qv.y);
            qdst[1] = __floats2half2_rn(qv.z, qv.w);
            __half2* ddst = (__half2*)(g_Dh + (size_t)row * DDIM + lane * 4);
            ddst[0] = __floats2half2_rn(dv.x, dv.y);
            ddst[1] = __floats2half2_rn(dv.z, dv.w);

            float pos = qv.x * dv.x + qv.y * dv.y + qv.z * dv.z + qv.w * dv.w;
            float neg = qv.x * nv.x + qv.y * nv.y + qv.z * nv.z + qv.w * nv.w;
            #pragma unroll
            for (int off = 16; off > 0; off >>= 1) {
                pos += __shfl_xor_sync(0xFFFFFFFFu, pos, off);
                neg += __shfl_xor_sync(0xFFFFFFFFu, neg, off);
            }
            if (lane == 0) {
                g_pos[row]   = pos;
                g_term1[row] = softplusf(neg - pos);
                g_rowmax_enc[row] = 0u;
            }
        }
    }
    __threadfence();
    __syncthreads();
    if (tid == 0) { atomicAdd(&g_prep, 1); spin_until(&g_prep, GRID_PERS); }
    __syncthreads();

    // ---------------- Phase 1: static-partition max-GEMM --------------------
    const int xr  = lane & 7;
    const int hcA = (lane >> 4) & 1;
    const int hcB = (lane >> 3) & 1;
    const uint32_t aRow    = (uint32_t)((wm * 64 + (lane & 15)) * 256);
    const uint32_t bRowOff = (uint32_t)((wn * 64 + ((lane >> 4) << 3) + (lane & 7)) * 256);

    const int iStart = (blockIdx.x * NITEMS) / GRID_PERS;
    const int iEnd   = ((blockIdx.x + 1) * NITEMS) / GRID_PERS;

    int i0 = iStart;
    while (i0 < iEnd) {
        const int rt = i0 >> 5;                         // row tile of this segment
        const int i1 = min(iEnd, (rt + 1) << 5);        // segment end (same rt)
        const int rowBase = rt * TILE_M;
        const int ct0 = (i0 & 31) * 4;                  // first global col tile
        const int ctN = (i1 - i0) * 4;                  // number of col tiles

        __syncthreads();   // all warps past previous segment's smem reads

        // prologue: group0 = A + B(ct0); group1 = B(ct0+1) (maybe empty)
        load_tileA_sw(sb + SMEM_A, g_Qh, rowBase, tid);
        load_tileB_sw(sb + SMEM_BR, g_Dh, (ct0 + 0) * TILE_N, tid);
        CP_COMMIT();
        if (ctN > 1)
            load_tileB_sw(sb + SMEM_BR + 32768, g_Dh, (ct0 + 1) * TILE_N, tid);
        CP_COMMIT();

        uint32_t rmax2[4][2];
        #pragma unroll
        for (int mi = 0; mi < 4; ++mi) { rmax2[mi][0] = 0xFC00FC00u; rmax2[mi][1] = 0xFC00FC00u; }

        for (int k = 0; k < ctN; ++k) {
            CP_WAIT1();            // group k complete (committed 2+k so far, ≤1 left)
            __syncthreads();
            // prefetch B(ct0+k+2); ALWAYS commit to keep group count uniform
            if (k + 2 < ctN)
                load_tileB_sw(sb + SMEM_BR + (uint32_t)(((k + 2) % 3) * 32768),
                              g_Dh, (ct0 + k + 2) * TILE_N, tid);
            CP_COMMIT();

            const uint32_t aBufBase = sb + SMEM_A + aRow;
            const uint32_t bBufBase = sb + SMEM_BR + (uint32_t)((k % 3) * 32768) + bRowOff;

            uint32_t acc[4][8][2];
            #pragma unroll
            for (int mi = 0; mi < 4; ++mi)
                #pragma unroll
                for (int ni = 0; ni < 8; ++ni) { acc[mi][ni][0] = 0u; acc[mi][ni][1] = 0u; }

            #pragma unroll
            for (int ks = 0; ks < 8; ++ks) {
                const uint32_t aCh = (uint32_t)(((ks * 2 + hcA) ^ xr) << 4);
                const uint32_t bCh = (uint32_t)(((ks * 2 + hcB) ^ xr) << 4);
                uint32_t a[4][4];
                #pragma unroll
                for (int mi = 0; mi < 4; ++mi)
                    ldsm4(a[mi], aBufBase + (uint32_t)(mi * 4096) + aCh);
                uint32_t b[4][4];
                #pragma unroll
                for (int np = 0; np < 4; ++np)
                    ldsm4(b[np], bBufBase + (uint32_t)(np * 4096) + bCh);
                #pragma unroll
                for (int mi = 0; mi < 4; ++mi)
                    #pragma unroll
                    for (int np = 0; np < 4; ++np) {
                        mma16816h(acc[mi][np * 2 + 0], a[mi], b[np][0], b[np][1]);
                        mma16816h(acc[mi][np * 2 + 1], a[mi], b[np][2], b[np][3]);
                    }
            }

            // diagonal mask: global col tile ct = ct0+k hits diag when dt in 0..3
            {
                const int dt = (ct0 + k) - 4 * rt;
                if (dt >= 0 && dt <= 3) {
                    const int coff = dt * 128;
                    #pragma unroll
                    for (int mi = 0; mi < 4; ++mi) {
                        int r0 = wm * 64 + mi * 16 + (lane >> 2);
                        #pragma unroll
                        for (int ni = 0; ni < 8; ++ni) {
                            int c0 = wn * 64 + ni * 8 + (lane & 3) * 2 + coff;
                            if (c0     == r0)     acc[mi][ni][0] = (acc[mi][ni][0] & 0xFFFF0000u) | NEGINF_LO;
                            if (c0 + 1 == r0)     acc[mi][ni][0] = (acc[mi][ni][0] & 0x0000FFFFu) | NEGINF_HI;
                            if (c0     == r0 + 8) acc[mi][ni][1] = (acc[mi][ni][1] & 0xFFFF0000u) | NEGINF_LO;
                            if (c0 + 1 == r0 + 8) acc[mi][ni][1] = (acc[mi][ni][1] & 0x0000FFFFu) | NEGINF_HI;
                        }
                    }
                }
            }
            #pragma unroll
            for (int mi = 0; mi < 4; ++mi)
                #pragma unroll
                for (int ni = 0; ni < 8; ++ni) {
                    rmax2[mi][0] = hmax2(rmax2[mi][0], acc[mi][ni][0]);
                    rmax2[mi][1] = hmax2(rmax2[mi][1], acc[mi][ni][1]);
                }
        }

        // segment epilogue: collapse + quad reduce + atomicMax (exact)
        {
            float rmax[8];
            #pragma unroll
            for (int mi = 0; mi < 4; ++mi)
                #pragma unroll
                for (int rr = 0; rr < 2; ++rr) {
                    __half2 h = *(__half2*)&rmax2[mi][rr];
                    rmax[mi * 2 + rr] = fmaxf(__low2float(h), __high2float(h));
                }
            #pragma unroll
            for (int i = 0; i < 8; ++i) {
                rmax[i] = fmaxf(rmax[i], __shfl_xor_sync(0xFFFFFFFFu, rmax[i], 1));
                rmax[i] = fmaxf(rmax[i], __shfl_xor_sync(0xFFFFFFFFu, rmax[i], 2));
            }
            if ((lane & 3) == 0) {
                #pragma unroll
                for (int mi = 0; mi < 4; ++mi) {
                    int rA = rowBase + wm * 64 + mi * 16 + (lane >> 2);
                    atomicMax(&g_rowmax_enc[rA],     enc_f(rmax[mi * 2 + 0]));
                    atomicMax(&g_rowmax_enc[rA + 8], enc_f(rmax[mi * 2 + 1]));
                }
            }
        }

        i0 = i1;
    }

    // ---------------- grid barrier 2 ----------------------------------------
    __threadfence();
    __syncthreads();
    if (tid == 0) { atomicAdd(&g_done, 1); spin_until(&g_done, GRID_PERS); }
    __syncthreads();
    __threadfence();

    // ---------------- Phase 2a: per-CTA deterministic partial sum -----------
    {
        float* sum = (float*)smem;
        const int r0 = blockIdx.x * ROWS_PER_CTA;
        const int r1 = (r0 + ROWS_PER_CTA < BSZ) ? (r0 + ROWS_PER_CTA) : BSZ;
        float s = 0.0f;
        for (int b = r0 + tid; b < r1; b += 512)
            s += g_term1[b] + softplusf(dec_f(g_rowmax_enc[b]) - g_pos[b]);
        sum[tid] = s;
        __syncthreads();
        #pragma unroll
        for (int off = 256; off > 0; off >>= 1) {
            if (tid < off) sum[tid] += sum[tid + off];
            __syncthreads();
        }
        if (tid == 0) { g_part[blockIdx.x] = sum[0]; __threadfence(); }
    }

    // ---------------- Phase 2b: last CTA combines ---------------------------
    __syncthreads();
    if (tid == 0) s_flag = (atomicAdd(&g_done2, 1) == GRID_PERS - 1) ? 1 : 0;
    __syncthreads();
    if (s_flag) {
        __threadfence();
        float* sum = (float*)smem;
        sum[tid] = (tid < GRID_PERS) ? g_part[tid] : 0.0f;
        __syncthreads();
        #pragma unroll
        for (int off = 256; off > 0; off >>= 1) {
            if (tid < off) sum[tid] += sum[tid + off];
            __syncthreads();
        }
        if (tid == 0) {
            out[0] = sum[0] / (2.0f * (float)BSZ);
            g_prep = 0; g_done = 0; g_done2 = 0;
            __threadfence();
        }
    }
}

// ---------------------------------------------------------------------------
extern "C" void kernel_launch(void* const* d_in, const int* in_sizes, int n_in,
                              void* d_out, int out_size) {
    const float* q  = (const float*)d_in[0];
    const float* dd = (const float*)d_in[1];
    const float* nd = (const float*)d_in[2];
    float* out = (float*)d_out;

    cudaFuncSetAttribute(mega_kernel, cudaFuncAttributeMaxDynamicSharedMemorySize, SMEM_TOTAL);
    mega_kernel<<<GRID_PERS, 512, SMEM_TOTAL>>>(q, dd, nd, out);
}